// round 3
// baseline (speedup 1.0000x reference)
#include <cuda_runtime.h>
#include <math.h>

// Problem constants
#define DW 128
#define DH 128
#define DD 128
#define NV (DW*DH*DD)          // 2097152 voxels
#define NS 16
#define HSL 128
#define WSL 128
#define PIX_PER_SLICE (HSL*WSL)
#define RES 1.5f
#define N_ITER 10

// Persistent state (device globals -> no allocations anywhere)
__device__ float g_b[NV];
__device__ float g_x[NV];
__device__ float g_r[NV];
__device__ float g_p[NV];
__device__ float g_Ap[NV];
// scalars: [0]=pAp  [1]=rr_new  [2]=rr  [3]=alpha  [4]=beta
__device__ double g_sc[6];

// ---------------------------------------------------------------------------
// Trilinear gather of one PSF tap (matches reference _corners semantics:
// out-of-bounds corners contribute exactly 0).
// ---------------------------------------------------------------------------
__device__ __forceinline__ float gather_tap(const float* __restrict__ v,
                                            float px, float py, float pz)
{
    // If any coord <= -1 or >= 128, every corner weight*value is zero.
    if (px <= -1.f || px >= 128.f || py <= -1.f || py >= 128.f ||
        pz <= -1.f || pz >= 128.f)
        return 0.f;

    float xf = floorf(px), yf = floorf(py), zf = floorf(pz);
    int ix = (int)xf, iy = (int)yf, iz = (int)zf;
    float fx = px - xf, fy = py - yf, fz = pz - zf;
    float gx = 1.f - fx, gy = 1.f - fy, gz = 1.f - fz;

    if (ix >= 0 && ix < DW-1 && iy >= 0 && iy < DH-1 && iz >= 0 && iz < DD-1) {
        // fast interior path: no per-corner checks
        const float* b0 = v + ((iz*DH + iy)*DW + ix);
        const float* b1 = b0 + DH*DW;
        float v000 = __ldg(b0),      v100 = __ldg(b0+1);
        float v010 = __ldg(b0+DW),   v110 = __ldg(b0+DW+1);
        float v001 = __ldg(b1),      v101 = __ldg(b1+1);
        float v011 = __ldg(b1+DW),   v111 = __ldg(b1+DW+1);
        return gz*(gy*(gx*v000 + fx*v100) + fy*(gx*v010 + fx*v110))
             + fz*(gy*(gx*v001 + fx*v101) + fy*(gx*v011 + fx*v111));
    }

    float acc = 0.f;
    #pragma unroll
    for (int dz = 0; dz < 2; dz++)
    #pragma unroll
    for (int dy = 0; dy < 2; dy++)
    #pragma unroll
    for (int dx = 0; dx < 2; dx++) {
        int X = ix + dx, Y = iy + dy, Z = iz + dz;
        if (X >= 0 && X < DW && Y >= 0 && Y < DH && Z >= 0 && Z < DD) {
            float w = (dx ? fx : gx) * (dy ? fy : gy) * (dz ? fz : gz);
            acc += w * __ldg(v + ((Z*DH + Y)*DW + X));
        }
    }
    return acc;
}

// ---------------------------------------------------------------------------
// Trilinear scatter-add of one PSF tap (exact adjoint of gather_tap)
// ---------------------------------------------------------------------------
__device__ __forceinline__ void scatter_tap(float* __restrict__ v,
                                            float px, float py, float pz, float c)
{
    if (px <= -1.f || px >= 128.f || py <= -1.f || py >= 128.f ||
        pz <= -1.f || pz >= 128.f)
        return;

    float xf = floorf(px), yf = floorf(py), zf = floorf(pz);
    int ix = (int)xf, iy = (int)yf, iz = (int)zf;
    float fx = px - xf, fy = py - yf, fz = pz - zf;
    float gx = 1.f - fx, gy = 1.f - fy, gz = 1.f - fz;

    if (ix >= 0 && ix < DW-1 && iy >= 0 && iy < DH-1 && iz >= 0 && iz < DD-1) {
        float* b0 = v + ((iz*DH + iy)*DW + ix);
        float* b1 = b0 + DH*DW;
        float cgz = c*gz, cfz = c*fz;
        atomicAdd(b0,       cgz*gy*gx);
        atomicAdd(b0+1,     cgz*gy*fx);
        atomicAdd(b0+DW,    cgz*fy*gx);
        atomicAdd(b0+DW+1,  cgz*fy*fx);
        atomicAdd(b1,       cfz*gy*gx);
        atomicAdd(b1+1,     cfz*gy*fx);
        atomicAdd(b1+DW,    cfz*fy*gx);
        atomicAdd(b1+DW+1,  cfz*fy*fx);
        return;
    }

    #pragma unroll
    for (int dz = 0; dz < 2; dz++)
    #pragma unroll
    for (int dy = 0; dy < 2; dy++)
    #pragma unroll
    for (int dx = 0; dx < 2; dx++) {
        int X = ix + dx, Y = iy + dy, Z = iz + dz;
        if (X >= 0 && X < DW && Y >= 0 && Y < DH && Z >= 0 && Z < DD) {
            float w = (dx ? fx : gx) * (dy ? fy : gy) * (dz ? fz : gz);
            atomicAdd(v + ((Z*DH + Y)*DW + X), c*w);
        }
    }
}

// ---------------------------------------------------------------------------
// Per-slice PSF tap constants into shared memory.
// Tap k (k = iz*9 + iy*3 + ix): offset (ax[ix], ax[iy], ax[iz]) in slice coords,
// rotated: c_k = R*offs_k + t + center.
// ---------------------------------------------------------------------------
__device__ __forceinline__ void load_slice_consts(const float* __restrict__ theta,
                                                  const float* __restrict__ psf,
                                                  int n, float sR[9],
                                                  float sC[27][3], float sPsf[27])
{
    int t = threadIdx.x;
    if (t < 9) sR[t] = theta[n*12 + (t/3)*4 + (t%3)];
    __syncthreads();
    if (t < 27) {
        float ox = (float)(t % 3)       - 1.f;
        float oy = (float)((t / 3) % 3) - 1.f;
        float oz = (float)(t / 9)       - 1.f;
        float tx = theta[n*12 + 3],  ty = theta[n*12 + 7],  tz = theta[n*12 + 11];
        sC[t][0] = sR[0]*ox + sR[1]*oy + sR[2]*oz + tx + 63.5f;
        sC[t][1] = sR[3]*ox + sR[4]*oy + sR[5]*oz + ty + 63.5f;
        sC[t][2] = sR[6]*ox + sR[7]*oy + sR[8]*oz + tz + 63.5f;
        sPsf[t]  = psf[t];
    }
    __syncthreads();
}

// ---------------------------------------------------------------------------
// Fused AtA: per pixel, gather slice value from vin, then scatter it back
// into vout (vout must be pre-zeroed).
// grid = (64, 1, 16), block = 256
// ---------------------------------------------------------------------------
__global__ void __launch_bounds__(256)
k_AtA(const float* __restrict__ theta, const float* __restrict__ psf,
      const float* __restrict__ vin, float* __restrict__ vout)
{
    __shared__ float sR[9];
    __shared__ float sC[27][3];
    __shared__ float sPsf[27];
    int n = blockIdx.z;
    load_slice_consts(theta, psf, n, sR, sC, sPsf);

    int pix = blockIdx.x * blockDim.x + threadIdx.x;
    int w = pix & (WSL-1);
    int h = pix >> 7;
    float u  = ((float)w - 63.5f) * RES;
    float vv = ((float)h - 63.5f) * RES;
    float bx = sR[0]*u + sR[1]*vv;
    float by = sR[3]*u + sR[4]*vv;
    float bz = sR[6]*u + sR[7]*vv;

    // center tap = k 13 (offset 0,0,0). Any other tap is within sqrt(3) of it;
    // trilinear support extends coords in (-1,128). Margin 3 is conservative.
    float cx = bx + sC[13][0], cy = by + sC[13][1], cz = bz + sC[13][2];
    if (cx < -3.f || cx > 130.f || cy < -3.f || cy > 130.f ||
        cz < -3.f || cz > 130.f)
        return;

    float sval = 0.f;
    for (int k = 0; k < 27; k++)
        sval += sPsf[k] * gather_tap(vin, bx + sC[k][0], by + sC[k][1], bz + sC[k][2]);

    if (sval != 0.f) {
        for (int k = 0; k < 27; k++)
            scatter_tap(vout, bx + sC[k][0], by + sC[k][1], bz + sC[k][2],
                        sval * sPsf[k]);
    }
}

// ---------------------------------------------------------------------------
// At only (for b = At(slices)). vout pre-zeroed.
// ---------------------------------------------------------------------------
__global__ void __launch_bounds__(256)
k_At(const float* __restrict__ theta, const float* __restrict__ psf,
     const float* __restrict__ slices, float* __restrict__ vout)
{
    __shared__ float sR[9];
    __shared__ float sC[27][3];
    __shared__ float sPsf[27];
    int n = blockIdx.z;
    load_slice_consts(theta, psf, n, sR, sC, sPsf);

    int pix = blockIdx.x * blockDim.x + threadIdx.x;
    int w = pix & (WSL-1);
    int h = pix >> 7;
    float u  = ((float)w - 63.5f) * RES;
    float vv = ((float)h - 63.5f) * RES;
    float bx = sR[0]*u + sR[1]*vv;
    float by = sR[3]*u + sR[4]*vv;
    float bz = sR[6]*u + sR[7]*vv;

    float cx = bx + sC[13][0], cy = by + sC[13][1], cz = bz + sC[13][2];
    if (cx < -3.f || cx > 130.f || cy < -3.f || cy > 130.f ||
        cz < -3.f || cz > 130.f)
        return;

    float sval = slices[n * PIX_PER_SLICE + pix];
    for (int k = 0; k < 27; k++)
        scatter_tap(vout, bx + sC[k][0], by + sC[k][1], bz + sC[k][2],
                    sval * sPsf[k]);
}

// ---------------------------------------------------------------------------
// Reductions + vector ops
// ---------------------------------------------------------------------------
__device__ __forceinline__ void reduce_add(double val, double* target)
{
    #pragma unroll
    for (int o = 16; o > 0; o >>= 1)
        val += __shfl_down_sync(0xffffffffu, val, o);
    __shared__ double sm[32];
    int lane = threadIdx.x & 31, wid = threadIdx.x >> 5;
    if (lane == 0) sm[wid] = val;
    __syncthreads();
    if (wid == 0) {
        val = (lane < (int)(blockDim.x >> 5)) ? sm[lane] : 0.0;
        #pragma unroll
        for (int o = 16; o > 0; o >>= 1)
            val += __shfl_down_sync(0xffffffffu, val, o);
        if (lane == 0) atomicAdd(target, val);
    }
}

// Zero a volume; optionally zero scalar slots (bitmask over slots 0..2)
__global__ void k_zero_vol(float* __restrict__ v, int scmask)
{
    int i = blockIdx.x * blockDim.x + threadIdx.x;
    if (i < NV) v[i] = 0.f;
    if (blockIdx.x == 0 && threadIdx.x == 0) {
        if (scmask & 1) g_sc[0] = 0.0;
        if (scmask & 2) g_sc[1] = 0.0;
        if (scmask & 4) g_sc[2] = 0.0;
    }
}

__global__ void k_copy(float* __restrict__ dst, const float* __restrict__ src)
{
    int i = blockIdx.x * blockDim.x + threadIdx.x;
    if (i < NV) dst[i] = src[i];
}

// r = b - Ap ; p = r ; rr += r.r  (slot 2 pre-zeroed)
__global__ void k_init_rp()
{
    int i = blockIdx.x * blockDim.x + threadIdx.x;
    double v = 0.0;
    if (i < NV) {
        float rv = g_b[i] - g_Ap[i];
        g_r[i] = rv;
        g_p[i] = rv;
        v = (double)rv * (double)rv;
    }
    reduce_add(v, &g_sc[2]);
}

// slot 0 (pAp) += p . Ap
__global__ void k_dot_pAp()
{
    int i = blockIdx.x * blockDim.x + threadIdx.x;
    double v = 0.0;
    if (i < NV) v = (double)g_p[i] * (double)g_Ap[i];
    reduce_add(v, &g_sc[0]);
}

__global__ void k_alpha() { g_sc[3] = g_sc[2] / g_sc[0]; }

// x += a p ; r -= a Ap ; rr_new += r.r  (slot 1 pre-zeroed)
__global__ void k_update_xr()
{
    float a = (float)g_sc[3];
    int i = blockIdx.x * blockDim.x + threadIdx.x;
    double v = 0.0;
    if (i < NV) {
        g_x[i] += a * g_p[i];
        float rv = g_r[i] - a * g_Ap[i];
        g_r[i] = rv;
        v = (double)rv * (double)rv;
    }
    reduce_add(v, &g_sc[1]);
}

__global__ void k_beta() { g_sc[4] = g_sc[1] / g_sc[2]; g_sc[2] = g_sc[1]; }

__global__ void k_update_p()
{
    float bt = (float)g_sc[4];
    int i = blockIdx.x * blockDim.x + threadIdx.x;
    if (i < NV) g_p[i] = g_r[i] + bt * g_p[i];
}

__global__ void k_relu_out(float* __restrict__ out)
{
    int i = blockIdx.x * blockDim.x + threadIdx.x;
    if (i < NV) out[i] = fmaxf(g_x[i], 0.f);
}

// ---------------------------------------------------------------------------
// Host driver (graph-capturable: kernel launches + symbol-address queries only)
// ---------------------------------------------------------------------------
extern "C" void kernel_launch(void* const* d_in, const int* in_sizes, int n_in,
                              void* d_out, int out_size)
{
    const float *theta = nullptr, *slices = nullptr, *volume = nullptr, *psf = nullptr;
    for (int i = 0; i < n_in; i++) {
        switch (in_sizes[i]) {
            case NS*12:            theta  = (const float*)d_in[i]; break;
            case NS*PIX_PER_SLICE: slices = (const float*)d_in[i]; break;
            case NV:               volume = (const float*)d_in[i]; break;
            case 27:               psf    = (const float*)d_in[i]; break;
            default: break;
        }
    }
    float* out = (float*)d_out;

    float *b, *x, *r, *p, *Ap;
    cudaGetSymbolAddress((void**)&b,  g_b);
    cudaGetSymbolAddress((void**)&x,  g_x);
    cudaGetSymbolAddress((void**)&r,  g_r);
    cudaGetSymbolAddress((void**)&p,  g_p);
    cudaGetSymbolAddress((void**)&Ap, g_Ap);
    (void)r; (void)p;

    const int VB = (NV + 255) / 256;       // 8192 blocks
    const dim3 gridS(PIX_PER_SLICE / 256, 1, NS);  // (64,1,16)

    // b = At(slices)
    k_zero_vol<<<VB, 256>>>(b, 0);
    k_At<<<gridS, 256>>>(theta, psf, slices, b);

    // x = x0 (input volume); Ap = AtA(x0); r = p = b - Ap; rr = r.r
    k_copy<<<VB, 256>>>(x, volume);
    k_zero_vol<<<VB, 256>>>(Ap, 4);        // zero Ap + rr slot
    k_AtA<<<gridS, 256>>>(theta, psf, volume, Ap);
    k_init_rp<<<VB, 256>>>();

    for (int it = 0; it < N_ITER; it++) {
        k_zero_vol<<<VB, 256>>>(Ap, 3);    // zero Ap + pAp + rr_new
        k_AtA<<<gridS, 256>>>(theta, psf, p, Ap);
        k_dot_pAp<<<VB, 256>>>();
        k_alpha<<<1, 1>>>();
        k_update_xr<<<VB, 256>>>();
        k_beta<<<1, 1>>>();
        k_update_p<<<VB, 256>>>();
    }

    k_relu_out<<<VB, 256>>>(out);
    (void)out_size;
}